// round 13
// baseline (speedup 1.0000x reference)
#include <cuda_runtime.h>
#include <cuda_bf16.h>
#include <stdint.h>

#define BDIM 32
#define SDIM 128
#define HDIM 512
#define VDIM 32000
#define TSTEPS 64
#define G4 (4*HDIM)

#define NBLK 148
#define NTHR 256
#define NWARPS (NBLK * (NTHR/32))   // 1184

#define KP 1536                     // packed K = 3 * HDIM
#define MROWS (TSTEPS*BDIM)         // 2048

typedef __nv_bfloat16 bf16;

// ---------------- scratch (no allocation allowed) ----------------
__device__ float g_hbuf[2*BDIM*HDIM];            // double-buffered h
__device__ float g_c[BDIM*HDIM];
__device__ float g_x[BDIM*HDIM];
__device__ float g_u0[BDIM*HDIM];                // sent @ W4[:, :H]^T
__device__ float g_ctx[BDIM*HDIM];
__device__ float g_scores[BDIM*SDIM];
__device__ float g_Hs[(size_t)TSTEPS*BDIM*HDIM]; // all h_t, row m = t*32+b
__device__ bf16  g_Ap[(size_t)MROWS*KP];         // [A_hi | A_lo | A_hi]
__device__ bf16  g_Bp[(size_t)VDIM*KP];          // [B_hi | B_hi | B_lo]  (~98 MB)

// barrier state (persists across replays; generation-based)
__device__ volatile unsigned g_bar_gen;
__device__ unsigned g_bar_cnt;

// ---------------- math helpers ----------------
__device__ __forceinline__ float tanh_fast(float x) {
    float ax = fabsf(x);
    float e  = __expf(-2.0f * ax);
    float r  = __fdividef(1.0f - e, 1.0f + e);
    return copysignf(r, x);
}
__device__ __forceinline__ float sigmoid_fast(float z) {
    float e = __expf(-z);
    return __fdividef(1.0f, 1.0f + e);
}
__device__ __forceinline__ uint32_t smem_u32(const void* p) {
    return (uint32_t)__cvta_generic_to_shared(p);
}

// ---------------- device-wide barrier ----------------
__device__ __forceinline__ void grid_sync() {
    __threadfence();
    __syncthreads();
    if (threadIdx.x == 0) {
        unsigned gen = g_bar_gen;
        if (atomicAdd(&g_bar_cnt, 1u) == NBLK - 1) {
            g_bar_cnt = 0;
            __threadfence();
            g_bar_gen = gen + 1;
        } else {
            while (g_bar_gen == gen) { }
        }
        __threadfence();
    }
    __syncthreads();
}

// ---------------- fused persistent recurrence ----------------
__global__ __launch_bounds__(NTHR) void recurrence_kernel(
    const float* __restrict__ w,     // [B,S,H]
    const float* __restrict__ sent,  // [B,H]
    const float* __restrict__ W2,    // [H]
    const float* __restrict__ W4,    // [H,2H]
    const float* __restrict__ Wih,   // [4H,H]
    const float* __restrict__ Whh,   // [4H,H]
    const float* __restrict__ bih,   // [4H]
    const float* __restrict__ bhh)   // [4H]
{
    __shared__ __align__(16) float sc[SDIM];
    __shared__ __align__(16) float part[NTHR];

    const int tid  = threadIdx.x;
    const int warp = tid >> 5;
    const int lane = tid & 31;
    const int gw   = blockIdx.x * (NTHR/32) + warp;   // 0..1183
    const int gid  = blockIdx.x * NTHR + tid;

    // ---- phase 0: zero h/c, compute u0 = sent @ W4[:, :H]^T ----
    if (gid < 2*BDIM*HDIM) g_hbuf[gid] = 0.f;
    if (gid < BDIM*HDIM)   g_c[gid]    = 0.f;
    if (gw < 1024) {
        const int j  = gw & (HDIM-1);
        const int b0 = (gw >> 9) * 16;
        const float* wrow = W4 + (size_t)j * (2*HDIM);
        float acc[16];
#pragma unroll
        for (int b = 0; b < 16; ++b) acc[b] = 0.f;
#pragma unroll
        for (int it = 0; it < 4; ++it) {
            int k4 = lane + it*32;
            float4 wv = __ldg(reinterpret_cast<const float4*>(wrow) + k4);
#pragma unroll
            for (int b = 0; b < 16; ++b) {
                float4 sv = __ldg(reinterpret_cast<const float4*>(sent + (size_t)(b0+b)*HDIM) + k4);
                acc[b] = fmaf(wv.x, sv.x, fmaf(wv.y, sv.y, fmaf(wv.z, sv.z, fmaf(wv.w, sv.w, acc[b]))));
            }
        }
#pragma unroll
        for (int b = 0; b < 16; ++b)
#pragma unroll
            for (int o = 16; o; o >>= 1) acc[b] += __shfl_xor_sync(0xffffffffu, acc[b], o);
        float v = 0.f;
#pragma unroll
        for (int b = 0; b < 16; ++b) if (lane == b) v = acc[b];
        if (lane < 16) g_u0[(size_t)(b0+lane)*HDIM + j] = v;
    }
    grid_sync();

    // ---- time loop ----
    for (int t = 0; t < TSTEPS; ++t) {
        const float* hcur = g_hbuf + (t & 1) * (BDIM*HDIM);
        float*       hnew = g_hbuf + ((t+1) & 1) * (BDIM*HDIM);

        // P1: scores[b,s] = sum_h tanh(w+h)*W2   (warp per (b,s))
        for (int task = gw; task < BDIM*SDIM; task += NWARPS) {
            int b = task >> 7, s = task & (SDIM-1);
            const float* wr = w + ((size_t)b * SDIM + s) * HDIM;
            const float* hb = hcur + (size_t)b * HDIM;
            float acc = 0.f;
#pragma unroll
            for (int it = 0; it < 16; ++it) {
                int h = lane + it*32;
                acc = fmaf(tanh_fast(__ldg(&wr[h]) + hb[h]), __ldg(&W2[h]), acc);
            }
#pragma unroll
            for (int o = 16; o; o >>= 1) acc += __shfl_xor_sync(0xffffffffu, acc, o);
            if (lane == 0) g_scores[b*SDIM + s] = acc;
        }
        grid_sync();

        // P2: softmax (redundant per block) + ctx  (block per (b, 128-h chunk))
        if (blockIdx.x < 128) {
            int b = blockIdx.x >> 2, hc = blockIdx.x & 3;
            if (warp == 0) {
                float v0 = g_scores[b*SDIM + lane];
                float v1 = g_scores[b*SDIM + lane + 32];
                float v2 = g_scores[b*SDIM + lane + 64];
                float v3 = g_scores[b*SDIM + lane + 96];
                float m = fmaxf(fmaxf(v0, v1), fmaxf(v2, v3));
#pragma unroll
                for (int o = 16; o; o >>= 1) m = fmaxf(m, __shfl_xor_sync(0xffffffffu, m, o));
                float e0 = __expf(v0 - m), e1 = __expf(v1 - m);
                float e2 = __expf(v2 - m), e3 = __expf(v3 - m);
                float sum = e0 + e1 + e2 + e3;
#pragma unroll
                for (int o = 16; o; o >>= 1) sum += __shfl_xor_sync(0xffffffffu, sum, o);
                float inv = __fdividef(1.0f, sum);
                sc[lane]    = e0*inv; sc[lane+32] = e1*inv;
                sc[lane+64] = e2*inv; sc[lane+96] = e3*inv;
            }
            __syncthreads();
            int h = hc*128 + (tid & 127);
            int s0 = (tid >> 7) * 64;
            const float* wb = w + (size_t)b * SDIM * HDIM;
            float acc = 0.f;
#pragma unroll 8
            for (int s = s0; s < s0 + 64; ++s)
                acc = fmaf(sc[s], __ldg(&wb[(size_t)s * HDIM + h]), acc);
            part[tid] = acc;
            __syncthreads();
            if (tid < 128) g_ctx[(size_t)b*HDIM + hc*128 + tid] = part[tid] + part[tid+128];
        }
        grid_sync();

        // P3: x[b,j] = tanh(u0 + ctx @ W4[:,H:].row(j))   (warp per (j, 16-b group))
        if (gw < 1024) {
            const int j  = gw & (HDIM-1);
            const int b0 = (gw >> 9) * 16;
            const float* wrow = W4 + (size_t)j * (2*HDIM) + HDIM;
            float acc[16];
#pragma unroll
            for (int b = 0; b < 16; ++b) acc[b] = 0.f;
#pragma unroll
            for (int it = 0; it < 4; ++it) {
                int k4 = lane + it*32;
                float4 wv = __ldg(reinterpret_cast<const float4*>(wrow) + k4);
#pragma unroll
                for (int b = 0; b < 16; ++b) {
                    float4 cv = *(reinterpret_cast<const float4*>(g_ctx + (size_t)(b0+b)*HDIM) + k4);
                    acc[b] = fmaf(wv.x, cv.x, fmaf(wv.y, cv.y, fmaf(wv.z, cv.z, fmaf(wv.w, cv.w, acc[b]))));
                }
            }
#pragma unroll
            for (int b = 0; b < 16; ++b)
#pragma unroll
                for (int o = 16; o; o >>= 1) acc[b] += __shfl_xor_sync(0xffffffffu, acc[b], o);
            float v = 0.f;
#pragma unroll
            for (int b = 0; b < 16; ++b) if (lane == b) v = acc[b];
            if (lane < 16)
                g_x[(size_t)(b0+lane)*HDIM + j] = tanh_fast(g_u0[(size_t)(b0+lane)*HDIM + j] + v);
        }
        grid_sync();

        // P4: gates (all 4 rows for jj) + LSTM update   (warp per (jj, 8-b group))
        for (int task = gw; task < HDIM*4; task += NWARPS) {
            const int jj = task & (HDIM-1);
            const int b0 = (task >> 9) * 8;
            float acc[4][8];
#pragma unroll
            for (int g = 0; g < 4; ++g)
#pragma unroll
                for (int b = 0; b < 8; ++b) acc[g][b] = 0.f;

            for (int it = 0; it < 4; ++it) {
                int k4 = lane + it*32;
                float4 wi[4], wh[4];
#pragma unroll
                for (int g = 0; g < 4; ++g) {
                    wi[g] = __ldg(reinterpret_cast<const float4*>(Wih + (size_t)(g*HDIM + jj)*HDIM) + k4);
                    wh[g] = __ldg(reinterpret_cast<const float4*>(Whh + (size_t)(g*HDIM + jj)*HDIM) + k4);
                }
#pragma unroll
                for (int b = 0; b < 8; ++b) {
                    float4 xv = *(reinterpret_cast<const float4*>(g_x  + (size_t)(b0+b)*HDIM) + k4);
                    float4 hv = *(reinterpret_cast<const float4*>(hcur + (size_t)(b0+b)*HDIM) + k4);
#pragma unroll
                    for (int g = 0; g < 4; ++g) {
                        acc[g][b] = fmaf(wi[g].x, xv.x, fmaf(wi[g].y, xv.y, fmaf(wi[g].z, xv.z, fmaf(wi[g].w, xv.w, acc[g][b]))));
                        acc[g][b] = fmaf(wh[g].x, hv.x, fmaf(wh[g].y, hv.y, fmaf(wh[g].z, hv.z, fmaf(wh[g].w, hv.w, acc[g][b]))));
                    }
                }
            }
#pragma unroll
            for (int g = 0; g < 4; ++g)
#pragma unroll
                for (int b = 0; b < 8; ++b)
#pragma unroll
                    for (int o = 16; o; o >>= 1) acc[g][b] += __shfl_xor_sync(0xffffffffu, acc[g][b], o);

            float ig = 0.f, fg = 0.f, gg = 0.f, og = 0.f;
#pragma unroll
            for (int b = 0; b < 8; ++b) if (lane == b) {
                ig = acc[0][b]; fg = acc[1][b]; gg = acc[2][b]; og = acc[3][b];
            }
            if (lane < 8) {
                int bb = b0 + lane;
                ig += __ldg(&bih[jj])          + __ldg(&bhh[jj]);
                fg += __ldg(&bih[HDIM + jj])   + __ldg(&bhh[HDIM + jj]);
                gg += __ldg(&bih[2*HDIM + jj]) + __ldg(&bhh[2*HDIM + jj]);
                og += __ldg(&bih[3*HDIM + jj]) + __ldg(&bhh[3*HDIM + jj]);
                float i_s = sigmoid_fast(ig);
                float f_s = sigmoid_fast(fg);
                float g_t = tanh_fast(gg);
                float o_s = sigmoid_fast(og);
                size_t idx = (size_t)bb * HDIM + jj;
                float c = fmaf(f_s, g_c[idx], i_s * g_t);
                float h = o_s * tanh_fast(c);
                g_c[idx]  = c;
                hnew[idx] = h;
                g_Hs[(size_t)t * (BDIM*HDIM) + idx] = h;
            }
        }
        grid_sync();
    }
}

// ---------------- split-pack kernels (fp32 -> bf16 hi/lo, K packed to 1536) ----------------
__global__ void pack_A() {
    int idx = blockIdx.x * 256 + threadIdx.x;       // < 2048*512
    int m = idx >> 9, k = idx & 511;
    float v = g_Hs[idx];
    bf16 hi = __float2bfloat16(v);
    bf16 lo = __float2bfloat16(v - __bfloat162float(hi));
    size_t base = (size_t)m * KP + k;
    g_Ap[base]        = hi;
    g_Ap[base + 512]  = lo;
    g_Ap[base + 1024] = hi;
}
__global__ void pack_B(const float* __restrict__ Wo) {
    int idx = blockIdx.x * 256 + threadIdx.x;       // < 32000*512
    int n = idx >> 9, k = idx & 511;
    float v = __ldg(&Wo[idx]);
    bf16 hi = __float2bfloat16(v);
    bf16 lo = __float2bfloat16(v - __bfloat162float(hi));
    size_t base = (size_t)n * KP + k;
    g_Bp[base]        = hi;
    g_Bp[base + 512]  = hi;
    g_Bp[base + 1024] = lo;
}

// ---------------- tensor-core out GEMM: C[2048,32000] = A' @ B'^T + b ----------------
// block tile 128x128, 8 warps (4 M x 2 N), warp tile 32x64, BK=32, cp.async 2-stage.
#define GK 32
#define NKB (KP/GK)   // 48

__device__ __forceinline__ void stage_load(bf16 (*As)[40], bf16 (*Bs)[40],
                                           const bf16* gA, const bf16* gB, int tid) {
#pragma unroll
    for (int i = 0; i < 2; ++i) {
        int ch = tid + i * 256;                 // 0..511
        int row = ch >> 2, kv = (ch & 3) << 3;  // 8 bf16 = 16B
        uint32_t sa = smem_u32(&As[row][kv]);
        const bf16* pa = gA + (size_t)row * KP + kv;
        asm volatile("cp.async.cg.shared.global [%0], [%1], 16;" :: "r"(sa), "l"(pa));
        uint32_t sb = smem_u32(&Bs[row][kv]);
        const bf16* pb = gB + (size_t)row * KP + kv;
        asm volatile("cp.async.cg.shared.global [%0], [%1], 16;" :: "r"(sb), "l"(pb));
    }
    asm volatile("cp.async.commit_group;");
}

__global__ __launch_bounds__(256) void out_gemm_tc(const float* __restrict__ bo,
                                                   float* __restrict__ out) {
    __shared__ __align__(16) bf16 As[2][128][40];
    __shared__ __align__(16) bf16 Bs[2][128][40];
    const int tid  = threadIdx.x;
    const int warp = tid >> 5, lane = tid & 31;
    const int wm = warp & 3, wn = warp >> 2;        // 4 x 2 warps
    const int bm = blockIdx.x * 128;                // 16 M tiles (fastest -> B' reuse in-wave)
    const int bn = blockIdx.y * 128;                // 250 N tiles
    const bf16* gA = g_Ap + (size_t)bm * KP;
    const bf16* gB = g_Bp + (size_t)bn * KP;

    float c[2][8][4];
#pragma unroll
    for (int i = 0; i < 2; ++i)
#pragma unroll
        for (int j = 0; j < 8; ++j)
#pragma unroll
            for (int k = 0; k < 4; ++k) c[i][j][k] = 0.f;

    stage_load(As[0], Bs[0], gA, gB, tid);
    asm volatile("cp.async.wait_group 0;");
    __syncthreads();

    const int a_r = wm*32 + (lane & 15);
    const int a_k = (lane >> 4) << 3;
    const int b_n = wn*64 + ((lane >> 4) << 3) + (lane & 7);
    const int b_k = ((lane >> 3) & 1) << 3;

    for (int kb = 0; kb < NKB; ++kb) {
        const int cur = kb & 1;
        if (kb + 1 < NKB)
            stage_load(As[cur^1], Bs[cur^1], gA + (kb+1)*GK, gB + (kb+1)*GK, tid);
#pragma unroll
        for (int ks = 0; ks < 2; ++ks) {
            uint32_t a[2][4];
#pragma unroll
            for (int cm = 0; cm < 2; ++cm) {
                uint32_t ad = smem_u32(&As[cur][a_r + cm*16][ks*16 + a_k]);
                asm volatile("ldmatrix.sync.aligned.m8n8.x4.shared.b16 {%0,%1,%2,%3}, [%4];"
                    : "=r"(a[cm][0]), "=r"(a[cm][1]), "=r"(a[cm][2]), "=r"(a[cm][3]) : "r"(ad));
            }
            uint32_t b[8][2];
#pragma unroll
            for (int p = 0; p < 4; ++p) {
                uint32_t r0, r1, r2, r3;
                uint32_t bd = smem_u32(&Bs[cur][b_n + p*16][ks*16 + b_k]);
                asm volatile("ldmatrix.sync.aligned.m8n8.x4.shared.b16 {%0,%1,%2,%3}, [%4];"
                    : "=r"(r0), "=r"(r1), "=r"(r2), "=r"(r3) : "r"(bd));
                b[2*p][0] = r0; b[2*p][1] = r1; b[2*p+1][0] = r2; b[2*p+1][1] = r3;
            }
#pragma unroll
            for (int cm = 0; cm < 2; ++cm)
#pragma unroll
                for (int cn = 0; cn < 8; ++cn)
                    asm volatile(
                        "mma.sync.aligned.m16n8k16.row.col.f32.bf16.bf16.f32 "
                        "{%0,%1,%2,%3}, {%4,%5,%6,%7}, {%8,%9}, {%0,%1,%2,%3};"
                        : "+f"(c[cm][cn][0]), "+f"(c[cm][cn][1]),
                          "+f"(c[cm][cn][2]), "+f"(c[cm][cn][3])
                        : "r"(a[cm][0]), "r"(a[cm][1]), "r"(a[cm][2]), "r"(a[cm][3]),
                          "r"(b[cn][0]), "r"(b[cn][1]));
        }
        if (kb + 1 < NKB) asm volatile("cp.async.wait_group 0;");
        __syncthreads();
    }

    // epilogue: row m = t*32+b -> out[b][t][n], add bias
    const int g  = lane >> 2;
    const int t2 = (lane & 3) * 2;
#pragma unroll
    for (int cm = 0; cm < 2; ++cm) {
#pragma unroll
        for (int half = 0; half < 2; ++half) {
            int m = bm + wm*32 + cm*16 + g + half*8;
            int b = m & 31, tt = m >> 5;
            float* orow = out + ((size_t)b * TSTEPS + tt) * VDIM;
#pragma unroll
            for (int cn = 0; cn < 8; ++cn) {
                int n = bn + wn*64 + cn*8 + t2;
                float2 r;
                r.x = c[cm][cn][half*2 + 0] + __ldg(&bo[n]);
                r.y = c[cm][cn][half*2 + 1] + __ldg(&bo[n + 1]);
                *reinterpret_cast<float2*>(&orow[n]) = r;
            }
        }
    }
}

__global__ void copy_hfin(float* __restrict__ dst) {
    int idx = blockIdx.x * 256 + threadIdx.x;
    dst[idx] = g_hbuf[idx];   // final h lives in buffer 0 (t=63 writes (63+1)&1 = 0)
}

// ---------------- launch ----------------
extern "C" void kernel_launch(void* const* d_in, const int* in_sizes, int n_in,
                              void* d_out, int out_size) {
    const float* w    = (const float*)d_in[0];   // [B,S,H]
    const float* sent = (const float*)d_in[1];   // [B,H]
    const float* W2   = (const float*)d_in[2];   // [H]
    const float* W4   = (const float*)d_in[3];   // [H,2H]
    const float* Wih  = (const float*)d_in[4];   // [4H,H]
    const float* Whh  = (const float*)d_in[5];   // [4H,H]
    const float* bih  = (const float*)d_in[6];   // [4H]
    const float* bhh  = (const float*)d_in[7];   // [4H]
    const float* Wo   = (const float*)d_in[8];   // [V,H]
    const float* bo   = (const float*)d_in[9];   // [V]
    float* out = (float*)d_out;

    pack_B<<<(VDIM*HDIM)/256, 256>>>(Wo);
    recurrence_kernel<<<NBLK, NTHR>>>(w, sent, W2, W4, Wih, Whh, bih, bhh);
    pack_A<<<(MROWS*HDIM)/256, 256>>>();
    out_gemm_tc<<<dim3(MROWS/128, VDIM/128), 256>>>(bo, out);
    copy_hfin<<<64, 256>>>(out + (size_t)BDIM * TSTEPS * VDIM);
}

// round 14
// speedup vs baseline: 1.0119x; 1.0119x over previous
#include <cuda_runtime.h>
#include <cuda_bf16.h>
#include <stdint.h>

#define BDIM 32
#define SDIM 128
#define HDIM 512
#define VDIM 32000
#define TSTEPS 64
#define G4 (4*HDIM)

#define NBLK 148
#define NTHR 256
#define NWARPS (NBLK * (NTHR/32))   // 1184

#define KP 1536                     // packed K = 3 * HDIM
#define MROWS (TSTEPS*BDIM)         // 2048

typedef __nv_bfloat16 bf16;

// ---------------- scratch (no allocation allowed) ----------------
__device__ float g_hbuf[2*BDIM*HDIM];            // double-buffered h
__device__ float g_c[BDIM*HDIM];
__device__ float g_x[BDIM*HDIM];
__device__ float g_u0[BDIM*HDIM];                // sent @ W4[:, :H]^T
__device__ float g_ctx[BDIM*HDIM];
__device__ float g_scores[BDIM*SDIM];
__device__ float g_Hs[(size_t)TSTEPS*BDIM*HDIM]; // all h_t, row m = t*32+b
__device__ bf16  g_Ap[(size_t)MROWS*KP];         // [A_hi | A_lo | A_hi]
__device__ bf16  g_Bp[(size_t)VDIM*KP];          // [B_hi | B_hi | B_lo]  (~98 MB)

// barrier state (persists across replays; generation-based)
__device__ volatile unsigned g_bar_gen;
__device__ unsigned g_bar_cnt;

// ---------------- math helpers ----------------
__device__ __forceinline__ float tanh_fast(float x) {
    float ax = fabsf(x);
    float e  = __expf(-2.0f * ax);
    float r  = __fdividef(1.0f - e, 1.0f + e);
    return copysignf(r, x);
}
__device__ __forceinline__ float sigmoid_fast(float z) {
    float e = __expf(-z);
    return __fdividef(1.0f, 1.0f + e);
}
__device__ __forceinline__ uint32_t smem_u32(const void* p) {
    return (uint32_t)__cvta_generic_to_shared(p);
}

// ---------------- device-wide barrier ----------------
__device__ __forceinline__ void grid_sync() {
    __threadfence();
    __syncthreads();
    if (threadIdx.x == 0) {
        unsigned gen = g_bar_gen;
        if (atomicAdd(&g_bar_cnt, 1u) == NBLK - 1) {
            g_bar_cnt = 0;
            __threadfence();
            g_bar_gen = gen + 1;
        } else {
            while (g_bar_gen == gen) { }
        }
        __threadfence();
    }
    __syncthreads();
}

// ---------------- fused persistent recurrence ----------------
__global__ __launch_bounds__(NTHR) void recurrence_kernel(
    const float* __restrict__ w,     // [B,S,H]
    const float* __restrict__ sent,  // [B,H]
    const float* __restrict__ W2,    // [H]
    const float* __restrict__ W4,    // [H,2H]
    const float* __restrict__ Wih,   // [4H,H]
    const float* __restrict__ Whh,   // [4H,H]
    const float* __restrict__ bih,   // [4H]
    const float* __restrict__ bhh)   // [4H]
{
    __shared__ __align__(16) float sc[SDIM];
    __shared__ __align__(16) float part[NTHR];

    const int tid  = threadIdx.x;
    const int warp = tid >> 5;
    const int lane = tid & 31;
    const int gw   = blockIdx.x * (NTHR/32) + warp;   // 0..1183
    const int gid  = blockIdx.x * NTHR + tid;

    // ---- phase 0: zero h/c, compute u0 = sent @ W4[:, :H]^T ----
    if (gid < 2*BDIM*HDIM) g_hbuf[gid] = 0.f;
    if (gid < BDIM*HDIM)   g_c[gid]    = 0.f;
    if (gw < 1024) {
        const int j  = gw & (HDIM-1);
        const int b0 = (gw >> 9) * 16;
        const float* wrow = W4 + (size_t)j * (2*HDIM);
        float acc[16];
#pragma unroll
        for (int b = 0; b < 16; ++b) acc[b] = 0.f;
#pragma unroll
        for (int it = 0; it < 4; ++it) {
            int k4 = lane + it*32;
            float4 wv = __ldg(reinterpret_cast<const float4*>(wrow) + k4);
#pragma unroll
            for (int b = 0; b < 16; ++b) {
                float4 sv = __ldg(reinterpret_cast<const float4*>(sent + (size_t)(b0+b)*HDIM) + k4);
                acc[b] = fmaf(wv.x, sv.x, fmaf(wv.y, sv.y, fmaf(wv.z, sv.z, fmaf(wv.w, sv.w, acc[b]))));
            }
        }
#pragma unroll
        for (int b = 0; b < 16; ++b)
#pragma unroll
            for (int o = 16; o; o >>= 1) acc[b] += __shfl_xor_sync(0xffffffffu, acc[b], o);
        float v = 0.f;
#pragma unroll
        for (int b = 0; b < 16; ++b) if (lane == b) v = acc[b];
        if (lane < 16) g_u0[(size_t)(b0+lane)*HDIM + j] = v;
    }
    grid_sync();

    // ---- time loop ----
    for (int t = 0; t < TSTEPS; ++t) {
        const float* hcur = g_hbuf + (t & 1) * (BDIM*HDIM);
        float*       hnew = g_hbuf + ((t+1) & 1) * (BDIM*HDIM);

        // P1: scores[b,s] = sum_h tanh(w+h)*W2   (warp per (b,s))
        for (int task = gw; task < BDIM*SDIM; task += NWARPS) {
            int b = task >> 7, s = task & (SDIM-1);
            const float* wr = w + ((size_t)b * SDIM + s) * HDIM;
            const float* hb = hcur + (size_t)b * HDIM;
            float acc = 0.f;
#pragma unroll
            for (int it = 0; it < 16; ++it) {
                int h = lane + it*32;
                acc = fmaf(tanh_fast(__ldg(&wr[h]) + hb[h]), __ldg(&W2[h]), acc);
            }
#pragma unroll
            for (int o = 16; o; o >>= 1) acc += __shfl_xor_sync(0xffffffffu, acc, o);
            if (lane == 0) g_scores[b*SDIM + s] = acc;
        }
        grid_sync();

        // P2: softmax (redundant per block) + ctx  (block per (b, 128-h chunk))
        if (blockIdx.x < 128) {
            int b = blockIdx.x >> 2, hc = blockIdx.x & 3;
            if (warp == 0) {
                float v0 = g_scores[b*SDIM + lane];
                float v1 = g_scores[b*SDIM + lane + 32];
                float v2 = g_scores[b*SDIM + lane + 64];
                float v3 = g_scores[b*SDIM + lane + 96];
                float m = fmaxf(fmaxf(v0, v1), fmaxf(v2, v3));
#pragma unroll
                for (int o = 16; o; o >>= 1) m = fmaxf(m, __shfl_xor_sync(0xffffffffu, m, o));
                float e0 = __expf(v0 - m), e1 = __expf(v1 - m);
                float e2 = __expf(v2 - m), e3 = __expf(v3 - m);
                float sum = e0 + e1 + e2 + e3;
#pragma unroll
                for (int o = 16; o; o >>= 1) sum += __shfl_xor_sync(0xffffffffu, sum, o);
                float inv = __fdividef(1.0f, sum);
                sc[lane]    = e0*inv; sc[lane+32] = e1*inv;
                sc[lane+64] = e2*inv; sc[lane+96] = e3*inv;
            }
            __syncthreads();
            int h = hc*128 + (tid & 127);
            int s0 = (tid >> 7) * 64;
            const float* wb = w + (size_t)b * SDIM * HDIM;
            float acc = 0.f;
#pragma unroll 8
            for (int s = s0; s < s0 + 64; ++s)
                acc = fmaf(sc[s], __ldg(&wb[(size_t)s * HDIM + h]), acc);
            part[tid] = acc;
            __syncthreads();
            if (tid < 128) g_ctx[(size_t)b*HDIM + hc*128 + tid] = part[tid] + part[tid+128];
        }
        grid_sync();

        // P3: x[b,j] = tanh(u0 + ctx @ W4[:,H:].row(j))   (warp per (j, 16-b group))
        if (gw < 1024) {
            const int j  = gw & (HDIM-1);
            const int b0 = (gw >> 9) * 16;
            const float* wrow = W4 + (size_t)j * (2*HDIM) + HDIM;
            float acc[16];
#pragma unroll
            for (int b = 0; b < 16; ++b) acc[b] = 0.f;
#pragma unroll
            for (int it = 0; it < 4; ++it) {
                int k4 = lane + it*32;
                float4 wv = __ldg(reinterpret_cast<const float4*>(wrow) + k4);
#pragma unroll
                for (int b = 0; b < 16; ++b) {
                    float4 cv = *(reinterpret_cast<const float4*>(g_ctx + (size_t)(b0+b)*HDIM) + k4);
                    acc[b] = fmaf(wv.x, cv.x, fmaf(wv.y, cv.y, fmaf(wv.z, cv.z, fmaf(wv.w, cv.w, acc[b]))));
                }
            }
#pragma unroll
            for (int b = 0; b < 16; ++b)
#pragma unroll
                for (int o = 16; o; o >>= 1) acc[b] += __shfl_xor_sync(0xffffffffu, acc[b], o);
            float v = 0.f;
#pragma unroll
            for (int b = 0; b < 16; ++b) if (lane == b) v = acc[b];
            if (lane < 16)
                g_x[(size_t)(b0+lane)*HDIM + j] = tanh_fast(g_u0[(size_t)(b0+lane)*HDIM + j] + v);
        }
        grid_sync();

        // P4: gates (all 4 rows for jj) + LSTM update   (warp per (jj, 8-b group))
        for (int task = gw; task < HDIM*4; task += NWARPS) {
            const int jj = task & (HDIM-1);
            const int b0 = (task >> 9) * 8;
            float acc[4][8];
#pragma unroll
            for (int g = 0; g < 4; ++g)
#pragma unroll
                for (int b = 0; b < 8; ++b) acc[g][b] = 0.f;

            for (int it = 0; it < 4; ++it) {
                int k4 = lane + it*32;
                float4 wi[4], wh[4];
#pragma unroll
                for (int g = 0; g < 4; ++g) {
                    wi[g] = __ldg(reinterpret_cast<const float4*>(Wih + (size_t)(g*HDIM + jj)*HDIM) + k4);
                    wh[g] = __ldg(reinterpret_cast<const float4*>(Whh + (size_t)(g*HDIM + jj)*HDIM) + k4);
                }
#pragma unroll
                for (int b = 0; b < 8; ++b) {
                    float4 xv = *(reinterpret_cast<const float4*>(g_x  + (size_t)(b0+b)*HDIM) + k4);
                    float4 hv = *(reinterpret_cast<const float4*>(hcur + (size_t)(b0+b)*HDIM) + k4);
#pragma unroll
                    for (int g = 0; g < 4; ++g) {
                        acc[g][b] = fmaf(wi[g].x, xv.x, fmaf(wi[g].y, xv.y, fmaf(wi[g].z, xv.z, fmaf(wi[g].w, xv.w, acc[g][b]))));
                        acc[g][b] = fmaf(wh[g].x, hv.x, fmaf(wh[g].y, hv.y, fmaf(wh[g].z, hv.z, fmaf(wh[g].w, hv.w, acc[g][b]))));
                    }
                }
            }
#pragma unroll
            for (int g = 0; g < 4; ++g)
#pragma unroll
                for (int b = 0; b < 8; ++b)
#pragma unroll
                    for (int o = 16; o; o >>= 1) acc[g][b] += __shfl_xor_sync(0xffffffffu, acc[g][b], o);

            float ig = 0.f, fg = 0.f, gg = 0.f, og = 0.f;
#pragma unroll
            for (int b = 0; b < 8; ++b) if (lane == b) {
                ig = acc[0][b]; fg = acc[1][b]; gg = acc[2][b]; og = acc[3][b];
            }
            if (lane < 8) {
                int bb = b0 + lane;
                ig += __ldg(&bih[jj])          + __ldg(&bhh[jj]);
                fg += __ldg(&bih[HDIM + jj])   + __ldg(&bhh[HDIM + jj]);
                gg += __ldg(&bih[2*HDIM + jj]) + __ldg(&bhh[2*HDIM + jj]);
                og += __ldg(&bih[3*HDIM + jj]) + __ldg(&bhh[3*HDIM + jj]);
                float i_s = sigmoid_fast(ig);
                float f_s = sigmoid_fast(fg);
                float g_t = tanh_fast(gg);
                float o_s = sigmoid_fast(og);
                size_t idx = (size_t)bb * HDIM + jj;
                float c = fmaf(f_s, g_c[idx], i_s * g_t);
                float h = o_s * tanh_fast(c);
                g_c[idx]  = c;
                hnew[idx] = h;
                g_Hs[(size_t)t * (BDIM*HDIM) + idx] = h;
            }
        }
        grid_sync();
    }
}

// ---------------- split-pack kernels (fp32 -> bf16 hi/lo, K packed to 1536) ----------------
__global__ void pack_A() {
    int idx = blockIdx.x * 256 + threadIdx.x;       // < 2048*512
    int m = idx >> 9, k = idx & 511;
    float v = g_Hs[idx];
    bf16 hi = __float2bfloat16(v);
    bf16 lo = __float2bfloat16(v - __bfloat162float(hi));
    size_t base = (size_t)m * KP + k;
    g_Ap[base]        = hi;
    g_Ap[base + 512]  = lo;
    g_Ap[base + 1024] = hi;
}
__global__ void pack_B(const float* __restrict__ Wo) {
    int idx = blockIdx.x * 256 + threadIdx.x;       // < 32000*512
    int n = idx >> 9, k = idx & 511;
    float v = __ldg(&Wo[idx]);
    bf16 hi = __float2bfloat16(v);
    bf16 lo = __float2bfloat16(v - __bfloat162float(hi));
    size_t base = (size_t)n * KP + k;
    g_Bp[base]        = hi;
    g_Bp[base + 512]  = hi;
    g_Bp[base + 1024] = lo;
}

// ---------------- tensor-core out GEMM: C[2048,32000] = A' @ B'^T + b ----------------
// block tile 128x128, 8 warps (4 M x 2 N), warp tile 32x64, BK=32, cp.async 2-stage.
#define GK 32
#define NKB (KP/GK)   // 48

__device__ __forceinline__ void stage_load(bf16 (*As)[40], bf16 (*Bs)[40],
                                           const bf16* gA, const bf16* gB, int tid) {
#pragma unroll
    for (int i = 0; i < 2; ++i) {
        int ch = tid + i * 256;                 // 0..511
        int row = ch >> 2, kv = (ch & 3) << 3;  // 8 bf16 = 16B
        uint32_t sa = smem_u32(&As[row][kv]);
        const bf16* pa = gA + (size_t)row * KP + kv;
        asm volatile("cp.async.cg.shared.global [%0], [%1], 16;" :: "r"(sa), "l"(pa));
        uint32_t sb = smem_u32(&Bs[row][kv]);
        const bf16* pb = gB + (size_t)row * KP + kv;
        asm volatile("cp.async.cg.shared.global [%0], [%1], 16;" :: "r"(sb), "l"(pb));
    }
    asm volatile("cp.async.commit_group;");
}

__global__ __launch_bounds__(256) void out_gemm_tc(const float* __restrict__ bo,
                                                   float* __restrict__ out) {
    __shared__ __align__(16) bf16 As[2][128][40];
    __shared__ __align__(16) bf16 Bs[2][128][40];
    const int tid  = threadIdx.x;
    const int warp = tid >> 5, lane = tid & 31;
    const int wm = warp & 3, wn = warp >> 2;        // 4 x 2 warps
    const int bm = blockIdx.x * 128;                // 16 M tiles (fastest -> B' reuse in-wave)
    const int bn = blockIdx.y * 128;                // 250 N tiles
    const bf16* gA = g_Ap + (size_t)bm * KP;
    const bf16* gB = g_Bp + (size_t)bn * KP;

    float c[2][8][4];
#pragma unroll
    for (int i = 0; i < 2; ++i)
#pragma unroll
        for (int j = 0; j < 8; ++j)
#pragma unroll
            for (int k = 0; k < 4; ++k) c[i][j][k] = 0.f;

    stage_load(As[0], Bs[0], gA, gB, tid);
    asm volatile("cp.async.wait_group 0;");
    __syncthreads();

    const int a_r = wm*32 + (lane & 15);
    const int a_k = (lane >> 4) << 3;
    const int b_n = wn*64 + ((lane >> 4) << 3) + (lane & 7);
    const int b_k = ((lane >> 3) & 1) << 3;

    for (int kb = 0; kb < NKB; ++kb) {
        const int cur = kb & 1;
        if (kb + 1 < NKB)
            stage_load(As[cur^1], Bs[cur^1], gA + (kb+1)*GK, gB + (kb+1)*GK, tid);
#pragma unroll
        for (int ks = 0; ks < 2; ++ks) {
            uint32_t a[2][4];
#pragma unroll
            for (int cm = 0; cm < 2; ++cm) {
                uint32_t ad = smem_u32(&As[cur][a_r + cm*16][ks*16 + a_k]);
                asm volatile("ldmatrix.sync.aligned.m8n8.x4.shared.b16 {%0,%1,%2,%3}, [%4];"
                    : "=r"(a[cm][0]), "=r"(a[cm][1]), "=r"(a[cm][2]), "=r"(a[cm][3]) : "r"(ad));
            }
            uint32_t b[8][2];
#pragma unroll
            for (int p = 0; p < 4; ++p) {
                uint32_t r0, r1, r2, r3;
                uint32_t bd = smem_u32(&Bs[cur][b_n + p*16][ks*16 + b_k]);
                asm volatile("ldmatrix.sync.aligned.m8n8.x4.shared.b16 {%0,%1,%2,%3}, [%4];"
                    : "=r"(r0), "=r"(r1), "=r"(r2), "=r"(r3) : "r"(bd));
                b[2*p][0] = r0; b[2*p][1] = r1; b[2*p+1][0] = r2; b[2*p+1][1] = r3;
            }
#pragma unroll
            for (int cm = 0; cm < 2; ++cm)
#pragma unroll
                for (int cn = 0; cn < 8; ++cn)
                    asm volatile(
                        "mma.sync.aligned.m16n8k16.row.col.f32.bf16.bf16.f32 "
                        "{%0,%1,%2,%3}, {%4,%5,%6,%7}, {%8,%9}, {%0,%1,%2,%3};"
                        : "+f"(c[cm][cn][0]), "+f"(c[cm][cn][1]),
                          "+f"(c[cm][cn][2]), "+f"(c[cm][cn][3])
                        : "r"(a[cm][0]), "r"(a[cm][1]), "r"(a[cm][2]), "r"(a[cm][3]),
                          "r"(b[cn][0]), "r"(b[cn][1]));
        }
        if (kb + 1 < NKB) asm volatile("cp.async.wait_group 0;");
        __syncthreads();
    }

    // epilogue: row m = t*32+b -> out[b][t][n], add bias
    const int g  = lane >> 2;
    const int t2 = (lane & 3) * 2;
#pragma unroll
    for (int cm = 0; cm < 2; ++cm) {
#pragma unroll
        for (int half = 0; half < 2; ++half) {
            int m = bm + wm*32 + cm*16 + g + half*8;
            int b = m & 31, tt = m >> 5;
            float* orow = out + ((size_t)b * TSTEPS + tt) * VDIM;
#pragma unroll
            for (int cn = 0; cn < 8; ++cn) {
                int n = bn + wn*64 + cn*8 + t2;
                float2 r;
                r.x = c[cm][cn][half*2 + 0] + __ldg(&bo[n]);
                r.y = c[cm][cn][half*2 + 1] + __ldg(&bo[n + 1]);
                *reinterpret_cast<float2*>(&orow[n]) = r;
            }
        }
    }
}

__global__ void copy_hfin(float* __restrict__ dst) {
    int idx = blockIdx.x * 256 + threadIdx.x;
    dst[idx] = g_hbuf[idx];   // final h lives in buffer 0 (t=63 writes (63+1)&1 = 0)
}

// ---------------- launch ----------------
extern "C" void kernel_launch(void* const* d_in, const int* in_sizes, int n_in,
                              void* d_out, int out_size) {
    const float* w    = (const float*)d_in[0];   // [B,S,H]
    const float* sent = (const float*)d_in[1];   // [B,H]
    const float* W2   = (const float*)d_in[2];   // [H]
    const float* W4   = (const float*)d_in[3];   // [H,2H]
    const float* Wih  = (const float*)d_in[4];   // [4H,H]
    const float* Whh  = (const float*)d_in[5];   // [4H,H]
    const float* bih  = (const float*)d_in[6];   // [4H]
    const float* bhh  = (const float*)d_in[7];   // [4H]
    const float* Wo   = (const float*)d_in[8];   // [V,H]
    const float* bo   = (const float*)d_in[9];   // [V]
    float* out = (float*)d_out;

    pack_B<<<(VDIM*HDIM)/256, 256>>>(Wo);
    recurrence_kernel<<<NBLK, NTHR>>>(w, sent, W2, W4, Wih, Whh, bih, bhh);
    pack_A<<<(MROWS*HDIM)/256, 256>>>();
    out_gemm_tc<<<dim3(MROWS/128, VDIM/128), 256>>>(bo, out);
    copy_hfin<<<64, 256>>>(out + (size_t)BDIM * TSTEPS * VDIM);
}